// round 16
// baseline (speedup 1.0000x reference)
#include <cuda_runtime.h>
#include <cuda_fp16.h>
#include <math.h>

#define NP_MAX 100000
#define NA_MAX 50000
#define E_MAX  2100000

// ---------------- device scratch ----------------
__device__ __half g_h[(size_t)(2 * NP_MAX + NA_MAX) * 256]; // h_cites | h_writes | h_wb (fp16)
__device__ float g_al_p[(size_t)NP_MAX * 16];
__device__ float g_al_a[(size_t)NA_MAX * 8];
__device__ float g_U[256 * 16 + 256 * 8];
__device__ int   g_rp[3 * (NP_MAX + 1)];
__device__ int   g_cnt[2 * NP_MAX + NA_MAX];
__device__ int   g_cur[2 * NP_MAX + NA_MAX];
__device__ int   g_ss[E_MAX];                               // CSR-sorted src indices

// ---------------- helpers ----------------
__device__ __forceinline__ float leaky(float x) { return x > 0.f ? x : 0.2f * x; }

__device__ __forceinline__ unsigned to_tf32(float f) {
    unsigned u;
    asm("cvt.rna.tf32.f32 %0, %1;" : "=r"(u) : "f"(f));
    return u;
}

__device__ __forceinline__ void mma_tf32(float* c, const unsigned* a, const unsigned* b) {
    asm("mma.sync.aligned.m16n8k8.row.col.f32.tf32.tf32.f32 "
        "{%0,%1,%2,%3},{%4,%5,%6,%7},{%8,%9},{%0,%1,%2,%3};"
        : "+f"(c[0]), "+f"(c[1]), "+f"(c[2]), "+f"(c[3])
        : "r"(a[0]), "r"(a[1]), "r"(a[2]), "r"(a[3]), "r"(b[0]), "r"(b[1]));
}

__device__ __forceinline__ void h8_to_f(uint4 v, float* f) {
    float2 t;
    t = __half22float2(*(__half2*)&v.x); f[0] = t.x; f[1] = t.y;
    t = __half22float2(*(__half2*)&v.y); f[2] = t.x; f[3] = t.y;
    t = __half22float2(*(__half2*)&v.z); f[4] = t.x; f[5] = t.y;
    t = __half22float2(*(__half2*)&v.w); f[6] = t.x; f[7] = t.y;
}

// ---------------- U = W @ a folding ----------------
__global__ void prep_u_kernel(const float* __restrict__ Wc, const float* __restrict__ asc,
                              const float* __restrict__ adc,
                              const float* __restrict__ Ww, const float* __restrict__ asw,
                              const float* __restrict__ adw,
                              const float* __restrict__ Wb, const float* __restrict__ asb,
                              const float* __restrict__ adb) {
    int d = threadIdx.x;
    float* Up = g_U;
    float* Ua = g_U + 256 * 16;
#pragma unroll
    for (int h = 0; h < 4; h++) {
        const float* wc = Wc + d * 256 + h * 64;
        const float* ww = Ww + d * 256 + h * 64;
        const float* wb = Wb + d * 256 + h * 64;
        float s0 = 0.f, s1 = 0.f, s2 = 0.f, s3 = 0.f, s4 = 0.f, s5 = 0.f;
        for (int c = 0; c < 64; c++) {
            s0 += wc[c] * asc[h * 64 + c];
            s1 += wc[c] * adc[h * 64 + c];
            s2 += ww[c] * adw[h * 64 + c];
            s3 += wb[c] * asb[h * 64 + c];
            s4 += ww[c] * asw[h * 64 + c];
            s5 += wb[c] * adb[h * 64 + c];
        }
        Up[d * 16 + 0 + h]  = s0;
        Up[d * 16 + 4 + h]  = s1;
        Up[d * 16 + 8 + h]  = s2;
        Up[d * 16 + 12 + h] = s3;
        Ua[d * 8 + 0 + h]   = s4;
        Ua[d * 8 + 4 + h]   = s5;
    }
}

// ---------------- AL = X @ U, smem-tiled ----------------
__global__ __launch_bounds__(256) void al_smem_kernel(const float* __restrict__ X,
                                                      const float* __restrict__ U,
                                                      float* __restrict__ AL,
                                                      int N, int ncols) {
    __shared__ float xs[32][257];
    __shared__ float us[256 * 16];
    int tid = threadIdx.x;
    int row0 = blockIdx.x * 32;

    for (int i = tid; i < 256 * ncols; i += 256) us[i] = U[i];
    for (int i = tid; i < 32 * 64; i += 256) {
        int r = i >> 6;
        int c4 = (i & 63) << 2;
        int gr = row0 + r;
        if (gr >= N) gr = N - 1;
        float4 v = *(const float4*)(X + (size_t)gr * 256 + c4);
        xs[r][c4 + 0] = v.x; xs[r][c4 + 1] = v.y;
        xs[r][c4 + 2] = v.z; xs[r][c4 + 3] = v.w;
    }
    __syncthreads();

    int row = tid & 31;
    int nper = ncols >> 3;
    int col0 = (tid >> 5) * nper;
    float s[2] = {0.f, 0.f};
    for (int k = 0; k < 256; k++) {
        float xv = xs[row][k];
#pragma unroll
        for (int q = 0; q < 2; q++)
            if (q < nper) s[q] += xv * us[k * ncols + col0 + q];
    }
    int gr = row0 + row;
    if (gr < N) {
#pragma unroll
        for (int q = 0; q < 2; q++)
            if (q < nper) AL[(size_t)gr * ncols + col0 + q] = s[q];
    }
}

// ---------------- tf32 GEMM (dual-output), R11 form ----------------
__global__ __launch_bounds__(256) void gemm_tf32_dual_kernel(
    const float* __restrict__ A,
    const float* __restrict__ B0, const float* __restrict__ B1,
    __half* __restrict__ C0, __half* __restrict__ C1, int M) {
    __shared__ unsigned As[2][16][132];
    __shared__ unsigned Bs[2][16][132];
    const float* B = (blockIdx.x < 2) ? B0 : B1;
    __half* C = (blockIdx.x < 2) ? C0 : C1;
    const int bm = blockIdx.y * 128;
    const int bn = (blockIdx.x & 1) * 128;
    const int tid = threadIdx.x;
    const int wid = tid >> 5, lane = tid & 31;
    const int warpM = wid & 3, warpN = wid >> 2;
    const int row0 = warpM * 32;
    const int nb0  = warpN * 64;
    const int g = lane >> 2, tig = lane & 3;

    float acc[2][8][4];
#pragma unroll
    for (int mi = 0; mi < 2; mi++)
#pragma unroll
        for (int ni = 0; ni < 8; ni++)
#pragma unroll
            for (int r = 0; r < 4; r++) acc[mi][ni][r] = 0.f;

    const int arow0 = tid / 4;
    const int acol  = (tid % 4) * 4;
    const int brow0 = tid / 32;
    const int bcol  = (tid % 32) * 4;

    {
#pragma unroll
        for (int r = 0; r < 2; r++) {
            int row = arow0 + r * 64;
            int grow = bm + row;
            if (grow >= M) grow = M - 1;
            float4 v = *(const float4*)(A + (size_t)grow * 256 + acol);
            As[0][acol + 0][row] = to_tf32(v.x);
            As[0][acol + 1][row] = to_tf32(v.y);
            As[0][acol + 2][row] = to_tf32(v.z);
            As[0][acol + 3][row] = to_tf32(v.w);
        }
#pragma unroll
        for (int r = 0; r < 2; r++) {
            int row = brow0 + r * 8;
            float4 v = *(const float4*)(B + (size_t)row * 256 + bn + bcol);
            Bs[0][row][bcol + 0] = to_tf32(v.x);
            Bs[0][row][bcol + 1] = to_tf32(v.y);
            Bs[0][row][bcol + 2] = to_tf32(v.z);
            Bs[0][row][bcol + 3] = to_tf32(v.w);
        }
    }
    __syncthreads();

    int buf = 0;
    for (int k0 = 16; k0 <= 256; k0 += 16) {
        const bool has_next = (k0 < 256);
        float4 pa[2], pb[2];
        if (has_next) {
#pragma unroll
            for (int r = 0; r < 2; r++) {
                int row = arow0 + r * 64;
                int grow = bm + row;
                if (grow >= M) grow = M - 1;
                pa[r] = *(const float4*)(A + (size_t)grow * 256 + k0 + acol);
            }
#pragma unroll
            for (int r = 0; r < 2; r++) {
                int row = brow0 + r * 8;
                pb[r] = *(const float4*)(B + (size_t)(k0 + row) * 256 + bn + bcol);
            }
        }
#pragma unroll
        for (int ks = 0; ks < 16; ks += 8) {
            unsigned af[2][4];
#pragma unroll
            for (int mi = 0; mi < 2; mi++) {
                int r = row0 + mi * 16 + g;
                af[mi][0] = As[buf][ks + tig][r];
                af[mi][1] = As[buf][ks + tig][r + 8];
                af[mi][2] = As[buf][ks + tig + 4][r];
                af[mi][3] = As[buf][ks + tig + 4][r + 8];
            }
            unsigned bf[8][2];
#pragma unroll
            for (int ni = 0; ni < 8; ni++) {
                int c = nb0 + ni * 8 + g;
                bf[ni][0] = Bs[buf][ks + tig][c];
                bf[ni][1] = Bs[buf][ks + tig + 4][c];
            }
#pragma unroll
            for (int mi = 0; mi < 2; mi++)
#pragma unroll
                for (int ni = 0; ni < 8; ni++)
                    mma_tf32(acc[mi][ni], af[mi], bf[ni]);
        }
        if (has_next) {
            int nbuf = buf ^ 1;
#pragma unroll
            for (int r = 0; r < 2; r++) {
                int row = arow0 + r * 64;
                As[nbuf][acol + 0][row] = to_tf32(pa[r].x);
                As[nbuf][acol + 1][row] = to_tf32(pa[r].y);
                As[nbuf][acol + 2][row] = to_tf32(pa[r].z);
                As[nbuf][acol + 3][row] = to_tf32(pa[r].w);
            }
#pragma unroll
            for (int r = 0; r < 2; r++) {
                int row = brow0 + r * 8;
                Bs[nbuf][row][bcol + 0] = to_tf32(pb[r].x);
                Bs[nbuf][row][bcol + 1] = to_tf32(pb[r].y);
                Bs[nbuf][row][bcol + 2] = to_tf32(pb[r].z);
                Bs[nbuf][row][bcol + 3] = to_tf32(pb[r].w);
            }
            __syncthreads();
            buf = nbuf;
        }
    }

#pragma unroll
    for (int mi = 0; mi < 2; mi++) {
        int row = bm + row0 + mi * 16 + g;
#pragma unroll
        for (int ni = 0; ni < 8; ni++) {
            int col = bn + nb0 + ni * 8 + 2 * tig;
            if (row < M)
                *(__half2*)(C + (size_t)row * 256 + col) =
                    __floats2half2_rn(acc[mi][ni][0], acc[mi][ni][1]);
            if (row + 8 < M)
                *(__half2*)(C + (size_t)(row + 8) * 256 + col) =
                    __floats2half2_rn(acc[mi][ni][2], acc[mi][ni][3]);
        }
    }
}

// ---------------- CSR build ----------------
__global__ void zero_cnt_kernel(int total) {
    int i = blockIdx.x * blockDim.x + threadIdx.x;
    if (i < total) g_cnt[i] = 0;
}

__global__ void hist3_kernel(const int* __restrict__ ec, int Ec,
                             const int* __restrict__ ew, int Ew,
                             const int* __restrict__ eb, int Eb) {
    int t = blockIdx.x * blockDim.x + threadIdx.x;
    if (t < Ec) {
        atomicAdd(&g_cnt[ec[Ec + t]], 1);
    } else if (t < Ec + Ew) {
        int e = t - Ec;
        atomicAdd(&g_cnt[NP_MAX + ew[Ew + e]], 1);
    } else if (t < Ec + Ew + Eb) {
        int e = t - Ec - Ew;
        atomicAdd(&g_cnt[2 * NP_MAX + eb[Eb + e]], 1);
    }
}

// hierarchical scan: warp shfl scan + one warp combines
__global__ __launch_bounds__(1024) void scan3_kernel(int np, int na, int* __restrict__ rp) {
    int rel = blockIdx.x;
    int n = (rel == 2) ? na : np;
    int off = rel * NP_MAX;
    int* rowptr = rp + rel * (NP_MAX + 1);
    const int* cnt = g_cnt + off;
    int* cursor = g_cur + off;

    __shared__ int wsum[32];
    __shared__ int s_carry;
    int tid = threadIdx.x;
    int lane = tid & 31, wid = tid >> 5;
    if (tid == 0) s_carry = 0;
    __syncthreads();

    for (int base = 0; base < n; base += 4096) {
        int idx = base + tid * 4;
        int v0 = (idx + 0 < n) ? cnt[idx + 0] : 0;
        int v1 = (idx + 1 < n) ? cnt[idx + 1] : 0;
        int v2 = (idx + 2 < n) ? cnt[idx + 2] : 0;
        int v3 = (idx + 3 < n) ? cnt[idx + 3] : 0;
        int s = v0 + v1 + v2 + v3;

        int isc = s;
#pragma unroll
        for (int o = 1; o < 32; o <<= 1) {
            int t = __shfl_up_sync(0xffffffffu, isc, o);
            if (lane >= o) isc += t;
        }
        if (lane == 31) wsum[wid] = isc;
        __syncthreads();
        if (wid == 0) {
            int w = wsum[lane];
#pragma unroll
            for (int o = 1; o < 32; o <<= 1) {
                int t = __shfl_up_sync(0xffffffffu, w, o);
                if (lane >= o) w += t;
            }
            wsum[lane] = w;
        }
        __syncthreads();

        int carry_in = s_carry;
        int wbase = (wid > 0) ? wsum[wid - 1] : 0;
        int excl = carry_in + wbase + (isc - s);
        if (idx + 0 < n) { rowptr[idx + 0] = excl; cursor[idx + 0] = excl; } excl += v0;
        if (idx + 1 < n) { rowptr[idx + 1] = excl; cursor[idx + 1] = excl; } excl += v1;
        if (idx + 2 < n) { rowptr[idx + 2] = excl; cursor[idx + 2] = excl; } excl += v2;
        if (idx + 3 < n) { rowptr[idx + 3] = excl; cursor[idx + 3] = excl; }
        __syncthreads();
        if (tid == 0) s_carry = carry_in + wsum[31];
        __syncthreads();
    }
    if (tid == 0) rowptr[n] = s_carry;
}

__global__ void scatter3_kernel(const int* __restrict__ ec, int Ec,
                                const int* __restrict__ ew, int Ew,
                                const int* __restrict__ eb, int Eb) {
    int t = blockIdx.x * blockDim.x + threadIdx.x;
    if (t < Ec) {
        int pos = atomicAdd(&g_cur[ec[Ec + t]], 1);
        g_ss[pos] = ec[t];
    } else if (t < Ec + Ew) {
        int e = t - Ec;
        int pos = atomicAdd(&g_cur[NP_MAX + ew[Ew + e]], 1);
        g_ss[Ec + pos] = ew[e];
    } else if (t < Ec + Ew + Eb) {
        int e = t - Ec - Ew;
        int pos = atomicAdd(&g_cur[2 * NP_MAX + eb[Eb + e]], 1);
        g_ss[Ec + Ew + pos] = eb[e];
    }
}

// ---------------- merged aggregation: unified per-row edge stream, registers -----
// One warp per dst row. Paper rows fuse cites+writes into ONE stream (t < n1 ->
// cites, else writes); separate den/acc pairs keep per-relation softmax exact.
// Batched issue 8/4/1 keeps up to 8 row-gathers in flight.
__global__ __launch_bounds__(256) void agg_all_kernel(
    const int* __restrict__ rp_c, const int* __restrict__ rp_w,
    const int* __restrict__ rp_b,
    const float* __restrict__ alp, const float* __restrict__ ala,
    const __half* __restrict__ h_c, const __half* __restrict__ h_w,
    const __half* __restrict__ h_b,
    const float* __restrict__ bc, const float* __restrict__ bw,
    const float* __restrict__ bb,
    float* __restrict__ out, int np, int na, int Ec, int Ew)
{
    int d = (blockIdx.x * blockDim.x + threadIdx.x) >> 5;
    if (d >= np + na) return;
    int lane = threadIdx.x & 31;
    int h = lane >> 3;
    int c = lane * 8;

    const bool paper = d < np;
    const int *ss1, *ss2;
    const float *als1, *als2;
    const __half *h1, *h2;
    int st1, st2, ho1, ho2, n1, n2;
    float ald1, ald2;
    if (paper) {
        int b1 = rp_c[d]; n1 = rp_c[d + 1] - b1;
        int b2 = rp_w[d]; n2 = rp_w[d + 1] - b2;
        ss1 = g_ss + b1;           als1 = alp; st1 = 16; ho1 = h;
        ald1 = __ldg(alp + (size_t)d * 16 + 4 + h); h1 = h_c;
        ss2 = g_ss + Ec + b2;      als2 = ala; st2 = 8;  ho2 = h;
        ald2 = __ldg(alp + (size_t)d * 16 + 8 + h); h2 = h_w;
    } else {
        int a = d - np;
        int b1 = rp_b[a]; n1 = rp_b[a + 1] - b1;
        ss1 = g_ss + Ec + Ew + b1; als1 = alp; st1 = 16; ho1 = 12 + h;
        ald1 = __ldg(ala + (size_t)a * 8 + 4 + h);  h1 = h_b;
        n2 = 0; ss2 = ss1; als2 = alp; st2 = 16; ho2 = ho1; ald2 = 0.f; h2 = h1;
    }
    const int ntot = n1 + n2;

    float acc1[8] = {0,0,0,0,0,0,0,0}, acc2[8] = {0,0,0,0,0,0,0,0};
    float den1 = 0.f, den2 = 0.f;
    float f[8];

    int i = 0;
    // tier 8: batch-issue indices, logits, rows
    for (; i + 7 < ntot; i += 8) {
        int sx[8]; bool r2[8]; float lg[8];
#pragma unroll
        for (int k = 0; k < 8; k++) {
            int t = i + k;
            r2[k] = (t >= n1);
            sx[k] = r2[k] ? __ldg(ss2 + (t - n1)) : __ldg(ss1 + t);
        }
#pragma unroll
        for (int k = 0; k < 8; k++)
            lg[k] = r2[k] ? (__ldg(als2 + (size_t)sx[k] * st2 + ho2) + ald2)
                          : (__ldg(als1 + (size_t)sx[k] * st1 + ho1) + ald1);
        uint4 r[8];
#pragma unroll
        for (int k = 0; k < 8; k++)
            r[k] = *((const uint4*)((r2[k] ? h2 : h1) + (size_t)sx[k] * 256) + lane);
        float ev[8];
#pragma unroll
        for (int k = 0; k < 8; k++) ev[k] = __expf(leaky(lg[k]));
#pragma unroll
        for (int k = 0; k < 8; k++) {
            float e1 = r2[k] ? 0.f : ev[k];
            float e2 = r2[k] ? ev[k] : 0.f;
            den1 += e1; den2 += e2;
            h8_to_f(r[k], f);
#pragma unroll
            for (int j = 0; j < 8; j++) { acc1[j] += e1 * f[j]; acc2[j] += e2 * f[j]; }
        }
    }
    // tier 4
    for (; i + 3 < ntot; i += 4) {
        int sx[4]; bool r2[4]; float lg[4];
#pragma unroll
        for (int k = 0; k < 4; k++) {
            int t = i + k;
            r2[k] = (t >= n1);
            sx[k] = r2[k] ? __ldg(ss2 + (t - n1)) : __ldg(ss1 + t);
        }
#pragma unroll
        for (int k = 0; k < 4; k++)
            lg[k] = r2[k] ? (__ldg(als2 + (size_t)sx[k] * st2 + ho2) + ald2)
                          : (__ldg(als1 + (size_t)sx[k] * st1 + ho1) + ald1);
        uint4 r[4];
#pragma unroll
        for (int k = 0; k < 4; k++)
            r[k] = *((const uint4*)((r2[k] ? h2 : h1) + (size_t)sx[k] * 256) + lane);
#pragma unroll
        for (int k = 0; k < 4; k++) {
            float ev = __expf(leaky(lg[k]));
            float e1 = r2[k] ? 0.f : ev;
            float e2 = r2[k] ? ev : 0.f;
            den1 += e1; den2 += e2;
            h8_to_f(r[k], f);
#pragma unroll
            for (int j = 0; j < 8; j++) { acc1[j] += e1 * f[j]; acc2[j] += e2 * f[j]; }
        }
    }
    // tier 1
    for (; i < ntot; i++) {
        bool r2 = (i >= n1);
        int s = r2 ? __ldg(ss2 + (i - n1)) : __ldg(ss1 + i);
        float lg = r2 ? (__ldg(als2 + (size_t)s * st2 + ho2) + ald2)
                      : (__ldg(als1 + (size_t)s * st1 + ho1) + ald1);
        uint4 r = *((const uint4*)((r2 ? h2 : h1) + (size_t)s * 256) + lane);
        float ev = __expf(leaky(lg));
        float e1 = r2 ? 0.f : ev;
        float e2 = r2 ? ev : 0.f;
        den1 += e1; den2 += e2;
        h8_to_f(r, f);
#pragma unroll
        for (int j = 0; j < 8; j++) { acc1[j] += e1 * f[j]; acc2[j] += e2 * f[j]; }
    }

    float inv1 = 1.f / (den1 + 1e-16f);
    float res[8];
    float* op = out + (size_t)d * 256 + c;
    if (paper) {
        float inv2 = 1.f / (den2 + 1e-16f);
        float4 b0c = *(const float4*)(bc + c), b1c = *(const float4*)(bc + c + 4);
        float4 b0w = *(const float4*)(bw + c), b1w = *(const float4*)(bw + c + 4);
        float bv[8] = {b0c.x + b0w.x, b0c.y + b0w.y, b0c.z + b0w.z, b0c.w + b0w.w,
                       b1c.x + b1w.x, b1c.y + b1w.y, b1c.z + b1w.z, b1c.w + b1w.w};
#pragma unroll
        for (int j = 0; j < 8; j++) {
            float v = acc1[j] * inv1 + acc2[j] * inv2 + bv[j];
            res[j] = v > 0.f ? v : expm1f(v);
        }
    } else {
        float4 b0 = *(const float4*)(bb + c), b1 = *(const float4*)(bb + c + 4);
        float bv[8] = {b0.x, b0.y, b0.z, b0.w, b1.x, b1.y, b1.z, b1.w};
#pragma unroll
        for (int j = 0; j < 8; j++) {
            float v = acc1[j] * inv1 + bv[j];
            res[j] = v > 0.f ? v : expm1f(v);
        }
    }
    __stcs((float4*)(op),     make_float4(res[0], res[1], res[2], res[3]));
    __stcs((float4*)(op + 4), make_float4(res[4], res[5], res[6], res[7]));
}

// ---------------- host launch (multi-stream fork/join, graph-capturable) --------
extern "C" void kernel_launch(void* const* d_in, const int* in_sizes, int n_in,
                              void* d_out, int out_size) {
    const float* x_p  = (const float*)d_in[0];
    const float* x_a  = (const float*)d_in[1];
    const int*   e_c  = (const int*)d_in[2];
    const int*   e_w  = (const int*)d_in[3];
    const int*   e_b  = (const int*)d_in[4];
    const float* W_c  = (const float*)d_in[5];
    const float* as_c = (const float*)d_in[6];
    const float* ad_c = (const float*)d_in[7];
    const float* b_c  = (const float*)d_in[8];
    const float* W_w  = (const float*)d_in[9];
    const float* as_w = (const float*)d_in[10];
    const float* ad_w = (const float*)d_in[11];
    const float* b_w  = (const float*)d_in[12];
    const float* W_b2 = (const float*)d_in[13];
    const float* as_b = (const float*)d_in[14];
    const float* ad_b = (const float*)d_in[15];
    const float* b_b  = (const float*)d_in[16];

    const int np = in_sizes[0] / 256;
    const int na = in_sizes[1] / 256;
    const int Ec = in_sizes[2] / 2;
    const int Ew = in_sizes[3] / 2;
    const int Eb = in_sizes[4] / 2;

    __half* h_base;
    float *alp, *ala, *U;
    int *rp;
    cudaGetSymbolAddress((void**)&h_base, g_h);
    cudaGetSymbolAddress((void**)&alp, g_al_p);
    cudaGetSymbolAddress((void**)&ala, g_al_a);
    cudaGetSymbolAddress((void**)&U, g_U);
    cudaGetSymbolAddress((void**)&rp, g_rp);

    __half* h_c = h_base;
    __half* h_w = h_base + (size_t)np * 256;
    __half* h_b = h_base + (size_t)(np + na) * 256;
    float* out_p = (float*)d_out;

    int* rp_c = rp;
    int* rp_w = rp + (NP_MAX + 1);
    int* rp_b = rp + 2 * (NP_MAX + 1);

    static cudaStream_t s_csr = nullptr, s_gemm = nullptr;
    static cudaEvent_t ev_root = nullptr, ev_csr = nullptr, ev_gemm = nullptr;
    if (!s_csr) {
        cudaStreamCreateWithFlags(&s_csr, cudaStreamNonBlocking);
        cudaStreamCreateWithFlags(&s_gemm, cudaStreamNonBlocking);
        cudaEventCreateWithFlags(&ev_root, cudaEventDisableTiming);
        cudaEventCreateWithFlags(&ev_csr, cudaEventDisableTiming);
        cudaEventCreateWithFlags(&ev_gemm, cudaEventDisableTiming);
    }
    cudaStream_t s0 = (cudaStream_t)0;

    // fork
    cudaEventRecord(ev_root, s0);
    cudaStreamWaitEvent(s_csr, ev_root, 0);
    cudaStreamWaitEvent(s_gemm, ev_root, 0);

    // branch 1 (default stream): attention logit precursors
    prep_u_kernel<<<1, 256, 0, s0>>>(W_c, as_c, ad_c, W_w, as_w, ad_w, W_b2, as_b, ad_b);
    al_smem_kernel<<<(np + 31) / 32, 256, 0, s0>>>(x_p, U,            alp, np, 16);
    al_smem_kernel<<<(na + 31) / 32, 256, 0, s0>>>(x_a, U + 256 * 16, ala, na, 8);

    // branch 2 (s_csr): CSR build
    int cnt_total = 2 * NP_MAX + NA_MAX;
    int Etot = Ec + Ew + Eb;
    zero_cnt_kernel<<<(cnt_total + 255) / 256, 256, 0, s_csr>>>(cnt_total);
    hist3_kernel<<<(Etot + 255) / 256, 256, 0, s_csr>>>(e_c, Ec, e_w, Ew, e_b, Eb);
    scan3_kernel<<<3, 1024, 0, s_csr>>>(np, na, rp);
    scatter3_kernel<<<(Etot + 255) / 256, 256, 0, s_csr>>>(e_c, Ec, e_w, Ew, e_b, Eb);
    cudaEventRecord(ev_csr, s_csr);

    // branch 3 (s_gemm): projections (R11 form: two dual launches)
    dim3 gp(4, (np + 127) / 128), ga(2, (na + 127) / 128);
    gemm_tf32_dual_kernel<<<gp, 256, 0, s_gemm>>>(x_p, W_c, W_b2, h_c, h_b, np);
    gemm_tf32_dual_kernel<<<ga, 256, 0, s_gemm>>>(x_a, W_w, W_w, h_w, h_w, na);
    cudaEventRecord(ev_gemm, s_gemm);

    // join on default stream
    cudaStreamWaitEvent(s0, ev_csr, 0);
    cudaStreamWaitEvent(s0, ev_gemm, 0);

    // merged gather aggregation, unified per-row edge stream
    agg_all_kernel<<<((np + na) * 32 + 255) / 256, 256, 0, s0>>>(
        rp_c, rp_w, rp_b, alp, ala, h_c, h_w, h_b,
        b_c, b_w, b_b, out_p, np, na, Ec, Ew);
}

// round 17
// speedup vs baseline: 2.1360x; 2.1360x over previous
#include <cuda_runtime.h>
#include <cuda_fp16.h>
#include <math.h>

#define NP_MAX 100000
#define NA_MAX 50000
#define E_MAX  2100000

// ---------------- device scratch ----------------
__device__ __half g_h[(size_t)(2 * NP_MAX + NA_MAX) * 256]; // h_cites | h_writes | h_wb (fp16)
__device__ float g_al_p[(size_t)NP_MAX * 16];
__device__ float g_al_a[(size_t)NA_MAX * 8];
__device__ float g_U[256 * 16 + 256 * 8];
__device__ int   g_rp[3 * (NP_MAX + 1)];
__device__ int   g_cnt[2 * NP_MAX + NA_MAX];
__device__ int   g_cur[2 * NP_MAX + NA_MAX];
__device__ int   g_ss[E_MAX];                               // CSR-sorted src indices

// ---------------- helpers ----------------
__device__ __forceinline__ float leaky(float x) { return x > 0.f ? x : 0.2f * x; }

__device__ __forceinline__ unsigned to_tf32(float f) {
    unsigned u;
    asm("cvt.rna.tf32.f32 %0, %1;" : "=r"(u) : "f"(f));
    return u;
}

__device__ __forceinline__ void mma_tf32(float* c, const unsigned* a, const unsigned* b) {
    asm("mma.sync.aligned.m16n8k8.row.col.f32.tf32.tf32.f32 "
        "{%0,%1,%2,%3},{%4,%5,%6,%7},{%8,%9},{%0,%1,%2,%3};"
        : "+f"(c[0]), "+f"(c[1]), "+f"(c[2]), "+f"(c[3])
        : "r"(a[0]), "r"(a[1]), "r"(a[2]), "r"(a[3]), "r"(b[0]), "r"(b[1]));
}

__device__ __forceinline__ void h8_to_f(uint4 v, float* f) {
    float2 t;
    t = __half22float2(*(__half2*)&v.x); f[0] = t.x; f[1] = t.y;
    t = __half22float2(*(__half2*)&v.y); f[2] = t.x; f[3] = t.y;
    t = __half22float2(*(__half2*)&v.z); f[4] = t.x; f[5] = t.y;
    t = __half22float2(*(__half2*)&v.w); f[6] = t.x; f[7] = t.y;
}

// ---------------- U = W @ a folding ----------------
__global__ void prep_u_kernel(const float* __restrict__ Wc, const float* __restrict__ asc,
                              const float* __restrict__ adc,
                              const float* __restrict__ Ww, const float* __restrict__ asw,
                              const float* __restrict__ adw,
                              const float* __restrict__ Wb, const float* __restrict__ asb,
                              const float* __restrict__ adb) {
    int d = threadIdx.x;
    float* Up = g_U;
    float* Ua = g_U + 256 * 16;
#pragma unroll
    for (int h = 0; h < 4; h++) {
        const float* wc = Wc + d * 256 + h * 64;
        const float* ww = Ww + d * 256 + h * 64;
        const float* wb = Wb + d * 256 + h * 64;
        float s0 = 0.f, s1 = 0.f, s2 = 0.f, s3 = 0.f, s4 = 0.f, s5 = 0.f;
        for (int c = 0; c < 64; c++) {
            s0 += wc[c] * asc[h * 64 + c];
            s1 += wc[c] * adc[h * 64 + c];
            s2 += ww[c] * adw[h * 64 + c];
            s3 += wb[c] * asb[h * 64 + c];
            s4 += ww[c] * asw[h * 64 + c];
            s5 += wb[c] * adb[h * 64 + c];
        }
        Up[d * 16 + 0 + h]  = s0;
        Up[d * 16 + 4 + h]  = s1;
        Up[d * 16 + 8 + h]  = s2;
        Up[d * 16 + 12 + h] = s3;
        Ua[d * 8 + 0 + h]   = s4;
        Ua[d * 8 + 4 + h]   = s5;
    }
}

// ---------------- AL = X @ U, smem-tiled ----------------
__global__ __launch_bounds__(256) void al_smem_kernel(const float* __restrict__ X,
                                                      const float* __restrict__ U,
                                                      float* __restrict__ AL,
                                                      int N, int ncols) {
    __shared__ float xs[32][257];
    __shared__ float us[256 * 16];
    int tid = threadIdx.x;
    int row0 = blockIdx.x * 32;

    for (int i = tid; i < 256 * ncols; i += 256) us[i] = U[i];
    for (int i = tid; i < 32 * 64; i += 256) {
        int r = i >> 6;
        int c4 = (i & 63) << 2;
        int gr = row0 + r;
        if (gr >= N) gr = N - 1;
        float4 v = *(const float4*)(X + (size_t)gr * 256 + c4);
        xs[r][c4 + 0] = v.x; xs[r][c4 + 1] = v.y;
        xs[r][c4 + 2] = v.z; xs[r][c4 + 3] = v.w;
    }
    __syncthreads();

    int row = tid & 31;
    int nper = ncols >> 3;
    int col0 = (tid >> 5) * nper;
    float s[2] = {0.f, 0.f};
    for (int k = 0; k < 256; k++) {
        float xv = xs[row][k];
#pragma unroll
        for (int q = 0; q < 2; q++)
            if (q < nper) s[q] += xv * us[k * ncols + col0 + q];
    }
    int gr = row0 + row;
    if (gr < N) {
#pragma unroll
        for (int q = 0; q < 2; q++)
            if (q < nper) AL[(size_t)gr * ncols + col0 + q] = s[q];
    }
}

// ---------------- tf32 GEMM (dual-output), pad 136: conflict-free LDS ----------
__global__ __launch_bounds__(256) void gemm_tf32_dual_kernel(
    const float* __restrict__ A,
    const float* __restrict__ B0, const float* __restrict__ B1,
    __half* __restrict__ C0, __half* __restrict__ C1, int M) {
    __shared__ unsigned As[2][16][136];
    __shared__ unsigned Bs[2][16][136];
    const float* B = (blockIdx.x < 2) ? B0 : B1;
    __half* C = (blockIdx.x < 2) ? C0 : C1;
    const int bm = blockIdx.y * 128;
    const int bn = (blockIdx.x & 1) * 128;
    const int tid = threadIdx.x;
    const int wid = tid >> 5, lane = tid & 31;
    const int warpM = wid & 3, warpN = wid >> 2;
    const int row0 = warpM * 32;
    const int nb0  = warpN * 64;
    const int g = lane >> 2, tig = lane & 3;

    float acc[2][8][4];
#pragma unroll
    for (int mi = 0; mi < 2; mi++)
#pragma unroll
        for (int ni = 0; ni < 8; ni++)
#pragma unroll
            for (int r = 0; r < 4; r++) acc[mi][ni][r] = 0.f;

    const int arow0 = tid / 4;
    const int acol  = (tid % 4) * 4;
    const int brow0 = tid / 32;
    const int bcol  = (tid % 32) * 4;

    {
#pragma unroll
        for (int r = 0; r < 2; r++) {
            int row = arow0 + r * 64;
            int grow = bm + row;
            if (grow >= M) grow = M - 1;
            float4 v = *(const float4*)(A + (size_t)grow * 256 + acol);
            As[0][acol + 0][row] = to_tf32(v.x);
            As[0][acol + 1][row] = to_tf32(v.y);
            As[0][acol + 2][row] = to_tf32(v.z);
            As[0][acol + 3][row] = to_tf32(v.w);
        }
#pragma unroll
        for (int r = 0; r < 2; r++) {
            int row = brow0 + r * 8;
            float4 v = *(const float4*)(B + (size_t)row * 256 + bn + bcol);
            Bs[0][row][bcol + 0] = to_tf32(v.x);
            Bs[0][row][bcol + 1] = to_tf32(v.y);
            Bs[0][row][bcol + 2] = to_tf32(v.z);
            Bs[0][row][bcol + 3] = to_tf32(v.w);
        }
    }
    __syncthreads();

    int buf = 0;
    for (int k0 = 16; k0 <= 256; k0 += 16) {
        const bool has_next = (k0 < 256);
        float4 pa[2], pb[2];
        if (has_next) {
#pragma unroll
            for (int r = 0; r < 2; r++) {
                int row = arow0 + r * 64;
                int grow = bm + row;
                if (grow >= M) grow = M - 1;
                pa[r] = *(const float4*)(A + (size_t)grow * 256 + k0 + acol);
            }
#pragma unroll
            for (int r = 0; r < 2; r++) {
                int row = brow0 + r * 8;
                pb[r] = *(const float4*)(B + (size_t)(k0 + row) * 256 + bn + bcol);
            }
        }
#pragma unroll
        for (int ks = 0; ks < 16; ks += 8) {
            unsigned af[2][4];
#pragma unroll
            for (int mi = 0; mi < 2; mi++) {
                int r = row0 + mi * 16 + g;
                af[mi][0] = As[buf][ks + tig][r];
                af[mi][1] = As[buf][ks + tig][r + 8];
                af[mi][2] = As[buf][ks + tig + 4][r];
                af[mi][3] = As[buf][ks + tig + 4][r + 8];
            }
            unsigned bf[8][2];
#pragma unroll
            for (int ni = 0; ni < 8; ni++) {
                int c = nb0 + ni * 8 + g;
                bf[ni][0] = Bs[buf][ks + tig][c];
                bf[ni][1] = Bs[buf][ks + tig + 4][c];
            }
#pragma unroll
            for (int mi = 0; mi < 2; mi++)
#pragma unroll
                for (int ni = 0; ni < 8; ni++)
                    mma_tf32(acc[mi][ni], af[mi], bf[ni]);
        }
        if (has_next) {
            int nbuf = buf ^ 1;
#pragma unroll
            for (int r = 0; r < 2; r++) {
                int row = arow0 + r * 64;
                As[nbuf][acol + 0][row] = to_tf32(pa[r].x);
                As[nbuf][acol + 1][row] = to_tf32(pa[r].y);
                As[nbuf][acol + 2][row] = to_tf32(pa[r].z);
                As[nbuf][acol + 3][row] = to_tf32(pa[r].w);
            }
#pragma unroll
            for (int r = 0; r < 2; r++) {
                int row = brow0 + r * 8;
                Bs[nbuf][row][bcol + 0] = to_tf32(pb[r].x);
                Bs[nbuf][row][bcol + 1] = to_tf32(pb[r].y);
                Bs[nbuf][row][bcol + 2] = to_tf32(pb[r].z);
                Bs[nbuf][row][bcol + 3] = to_tf32(pb[r].w);
            }
            __syncthreads();
            buf = nbuf;
        }
    }

#pragma unroll
    for (int mi = 0; mi < 2; mi++) {
        int row = bm + row0 + mi * 16 + g;
#pragma unroll
        for (int ni = 0; ni < 8; ni++) {
            int col = bn + nb0 + ni * 8 + 2 * tig;
            if (row < M)
                *(__half2*)(C + (size_t)row * 256 + col) =
                    __floats2half2_rn(acc[mi][ni][0], acc[mi][ni][1]);
            if (row + 8 < M)
                *(__half2*)(C + (size_t)(row + 8) * 256 + col) =
                    __floats2half2_rn(acc[mi][ni][2], acc[mi][ni][3]);
        }
    }
}

// ---------------- CSR build ----------------
__global__ void zero_cnt_kernel(int total) {
    int i = blockIdx.x * blockDim.x + threadIdx.x;
    if (i < total) g_cnt[i] = 0;
}

__global__ void hist3_kernel(const int* __restrict__ ec, int Ec,
                             const int* __restrict__ ew, int Ew,
                             const int* __restrict__ eb, int Eb) {
    int t = blockIdx.x * blockDim.x + threadIdx.x;
    if (t < Ec) {
        atomicAdd(&g_cnt[ec[Ec + t]], 1);
    } else if (t < Ec + Ew) {
        int e = t - Ec;
        atomicAdd(&g_cnt[NP_MAX + ew[Ew + e]], 1);
    } else if (t < Ec + Ew + Eb) {
        int e = t - Ec - Ew;
        atomicAdd(&g_cnt[2 * NP_MAX + eb[Eb + e]], 1);
    }
}

// hierarchical scan: warp shfl scan + one warp combines
__global__ __launch_bounds__(1024) void scan3_kernel(int np, int na, int* __restrict__ rp) {
    int rel = blockIdx.x;
    int n = (rel == 2) ? na : np;
    int off = rel * NP_MAX;
    int* rowptr = rp + rel * (NP_MAX + 1);
    const int* cnt = g_cnt + off;
    int* cursor = g_cur + off;

    __shared__ int wsum[32];
    __shared__ int s_carry;
    int tid = threadIdx.x;
    int lane = tid & 31, wid = tid >> 5;
    if (tid == 0) s_carry = 0;
    __syncthreads();

    for (int base = 0; base < n; base += 4096) {
        int idx = base + tid * 4;
        int v0 = (idx + 0 < n) ? cnt[idx + 0] : 0;
        int v1 = (idx + 1 < n) ? cnt[idx + 1] : 0;
        int v2 = (idx + 2 < n) ? cnt[idx + 2] : 0;
        int v3 = (idx + 3 < n) ? cnt[idx + 3] : 0;
        int s = v0 + v1 + v2 + v3;

        int isc = s;
#pragma unroll
        for (int o = 1; o < 32; o <<= 1) {
            int t = __shfl_up_sync(0xffffffffu, isc, o);
            if (lane >= o) isc += t;
        }
        if (lane == 31) wsum[wid] = isc;
        __syncthreads();
        if (wid == 0) {
            int w = wsum[lane];
#pragma unroll
            for (int o = 1; o < 32; o <<= 1) {
                int t = __shfl_up_sync(0xffffffffu, w, o);
                if (lane >= o) w += t;
            }
            wsum[lane] = w;
        }
        __syncthreads();

        int carry_in = s_carry;
        int wbase = (wid > 0) ? wsum[wid - 1] : 0;
        int excl = carry_in + wbase + (isc - s);
        if (idx + 0 < n) { rowptr[idx + 0] = excl; cursor[idx + 0] = excl; } excl += v0;
        if (idx + 1 < n) { rowptr[idx + 1] = excl; cursor[idx + 1] = excl; } excl += v1;
        if (idx + 2 < n) { rowptr[idx + 2] = excl; cursor[idx + 2] = excl; } excl += v2;
        if (idx + 3 < n) { rowptr[idx + 3] = excl; cursor[idx + 3] = excl; }
        __syncthreads();
        if (tid == 0) s_carry = carry_in + wsum[31];
        __syncthreads();
    }
    if (tid == 0) rowptr[n] = s_carry;
}

__global__ void scatter3_kernel(const int* __restrict__ ec, int Ec,
                                const int* __restrict__ ew, int Ew,
                                const int* __restrict__ eb, int Eb) {
    int t = blockIdx.x * blockDim.x + threadIdx.x;
    if (t < Ec) {
        int pos = atomicAdd(&g_cur[ec[Ec + t]], 1);
        g_ss[pos] = ec[t];
    } else if (t < Ec + Ew) {
        int e = t - Ec;
        int pos = atomicAdd(&g_cur[NP_MAX + ew[Ew + e]], 1);
        g_ss[Ec + pos] = ew[e];
    } else if (t < Ec + Ew + Eb) {
        int e = t - Ec - Ew;
        int pos = atomicAdd(&g_cur[2 * NP_MAX + eb[Eb + e]], 1);
        g_ss[Ec + Ew + pos] = eb[e];
    }
}

// ---------------- aggregation inner loop: batched unroll-8 / 2 / 1 -------------
__device__ __forceinline__ float agg_rel(const int* __restrict__ ssrc, int beg, int end,
                                         const float* __restrict__ als, int ss, int hoff,
                                         float ald, const __half* __restrict__ hmat,
                                         int lane, float* acc) {
    float den = 0.f;
    float f[8];
    int i = beg;
    for (; i + 7 < end; i += 8) {
        int sx[8];
#pragma unroll
        for (int k = 0; k < 8; k++) sx[k] = __ldg(ssrc + i + k);
        float av[8];
#pragma unroll
        for (int k = 0; k < 8; k++) av[k] = __ldg(als + (size_t)sx[k] * ss + hoff);
        uint4 r[8];
#pragma unroll
        for (int k = 0; k < 8; k++)
            r[k] = *((const uint4*)(hmat + (size_t)sx[k] * 256) + lane);
        float ev[8];
#pragma unroll
        for (int k = 0; k < 8; k++) { ev[k] = __expf(leaky(av[k] + ald)); den += ev[k]; }
#pragma unroll
        for (int k = 0; k < 8; k++) {
            h8_to_f(r[k], f);
#pragma unroll
            for (int j = 0; j < 8; j++) acc[j] += ev[k] * f[j];
        }
    }
    for (; i + 1 < end; i += 2) {
        int s0 = __ldg(ssrc + i), s1 = __ldg(ssrc + i + 1);
        float a0 = __ldg(als + (size_t)s0 * ss + hoff);
        float a1 = __ldg(als + (size_t)s1 * ss + hoff);
        uint4 r0 = *((const uint4*)(hmat + (size_t)s0 * 256) + lane);
        uint4 r1 = *((const uint4*)(hmat + (size_t)s1 * 256) + lane);
        float e0 = __expf(leaky(a0 + ald));
        float e1 = __expf(leaky(a1 + ald));
        den += e0 + e1;
        float f1v[8];
        h8_to_f(r0, f); h8_to_f(r1, f1v);
#pragma unroll
        for (int j = 0; j < 8; j++) acc[j] += e0 * f[j] + e1 * f1v[j];
    }
    if (i < end) {
        int s = __ldg(ssrc + i);
        float ew = __expf(leaky(__ldg(als + (size_t)s * ss + hoff) + ald));
        den += ew;
        uint4 r0 = *((const uint4*)(hmat + (size_t)s * 256) + lane);
        h8_to_f(r0, f);
#pragma unroll
        for (int j = 0; j < 8; j++) acc[j] += ew * f[j];
    }
    return den;
}

// ---------------- merged aggregation: paper (cites+writes) and author (wb) -------
__global__ __launch_bounds__(256) void agg_all_kernel(
    const int* __restrict__ rp_c, const int* __restrict__ rp_w,
    const int* __restrict__ rp_b,
    const float* __restrict__ alp, const float* __restrict__ ala,
    const __half* __restrict__ h_c, const __half* __restrict__ h_w,
    const __half* __restrict__ h_b,
    const float* __restrict__ bc, const float* __restrict__ bw,
    const float* __restrict__ bb,
    float* __restrict__ out, int np, int na, int Ec, int Ew)
{
    int d = (blockIdx.x * blockDim.x + threadIdx.x) >> 5;
    if (d >= np + na) return;
    int lane = threadIdx.x & 31;
    int h = lane >> 3;
    int c = lane * 8;
    float acc[8] = {0.f, 0.f, 0.f, 0.f, 0.f, 0.f, 0.f, 0.f};
    float res[8];

    if (d < np) {
        {   // cites: dst alp[d*16+4+h], src alp[s*16+0+h]
            float ald = __ldg(alp + (size_t)d * 16 + 4 + h);
            float den = agg_rel(g_ss, rp_c[d], rp_c[d + 1], alp, 16, h, ald, h_c, lane, acc);
            float inv = 1.f / (den + 1e-16f);
#pragma unroll
            for (int j = 0; j < 8; j++) { res[j] = acc[j] * inv; acc[j] = 0.f; }
        }
        {   // writes: dst alp[d*16+8+h], src ala[s*8+0+h]
            float ald = __ldg(alp + (size_t)d * 16 + 8 + h);
            float den = agg_rel(g_ss + Ec, rp_w[d], rp_w[d + 1], ala, 8, h, ald, h_w, lane, acc);
            float inv = 1.f / (den + 1e-16f);
#pragma unroll
            for (int j = 0; j < 8; j++) res[j] += acc[j] * inv;
        }
        float4 b0c = *(const float4*)(bc + c), b1c = *(const float4*)(bc + c + 4);
        float4 b0w = *(const float4*)(bw + c), b1w = *(const float4*)(bw + c + 4);
        float bv[8] = {b0c.x + b0w.x, b0c.y + b0w.y, b0c.z + b0w.z, b0c.w + b0w.w,
                       b1c.x + b1w.x, b1c.y + b1w.y, b1c.z + b1w.z, b1c.w + b1w.w};
        float* op = out + (size_t)d * 256 + c;
#pragma unroll
        for (int j = 0; j < 8; j++) {
            float v = res[j] + bv[j];
            res[j] = v > 0.f ? v : expm1f(v);
        }
        __stcs((float4*)(op),     make_float4(res[0], res[1], res[2], res[3]));
        __stcs((float4*)(op + 4), make_float4(res[4], res[5], res[6], res[7]));
    } else {
        int a = d - np;
        float ald = __ldg(ala + (size_t)a * 8 + 4 + h);
        float den = agg_rel(g_ss + Ec + Ew, rp_b[a], rp_b[a + 1], alp, 16, 12 + h,
                            ald, h_b, lane, acc);
        float inv = 1.f / (den + 1e-16f);
        float4 b0 = *(const float4*)(bb + c), b1 = *(const float4*)(bb + c + 4);
        float bv[8] = {b0.x, b0.y, b0.z, b0.w, b1.x, b1.y, b1.z, b1.w};
        float* op = out + (size_t)d * 256 + c;
#pragma unroll
        for (int j = 0; j < 8; j++) {
            float v = acc[j] * inv + bv[j];
            res[j] = v > 0.f ? v : expm1f(v);
        }
        __stcs((float4*)(op),     make_float4(res[0], res[1], res[2], res[3]));
        __stcs((float4*)(op + 4), make_float4(res[4], res[5], res[6], res[7]));
    }
}

// ---------------- host launch (multi-stream fork/join, graph-capturable) --------
extern "C" void kernel_launch(void* const* d_in, const int* in_sizes, int n_in,
                              void* d_out, int out_size) {
    const float* x_p  = (const float*)d_in[0];
    const float* x_a  = (const float*)d_in[1];
    const int*   e_c  = (const int*)d_in[2];
    const int*   e_w  = (const int*)d_in[3];
    const int*   e_b  = (const int*)d_in[4];
    const float* W_c  = (const float*)d_in[5];
    const float* as_c = (const float*)d_in[6];
    const float* ad_c = (const float*)d_in[7];
    const float* b_c  = (const float*)d_in[8];
    const float* W_w  = (const float*)d_in[9];
    const float* as_w = (const float*)d_in[10];
    const float* ad_w = (const float*)d_in[11];
    const float* b_w  = (const float*)d_in[12];
    const float* W_b2 = (const float*)d_in[13];
    const float* as_b = (const float*)d_in[14];
    const float* ad_b = (const float*)d_in[15];
    const float* b_b  = (const float*)d_in[16];

    const int np = in_sizes[0] / 256;
    const int na = in_sizes[1] / 256;
    const int Ec = in_sizes[2] / 2;
    const int Ew = in_sizes[3] / 2;
    const int Eb = in_sizes[4] / 2;

    __half* h_base;
    float *alp, *ala, *U;
    int *rp;
    cudaGetSymbolAddress((void**)&h_base, g_h);
    cudaGetSymbolAddress((void**)&alp, g_al_p);
    cudaGetSymbolAddress((void**)&ala, g_al_a);
    cudaGetSymbolAddress((void**)&U, g_U);
    cudaGetSymbolAddress((void**)&rp, g_rp);

    __half* h_c = h_base;
    __half* h_w = h_base + (size_t)np * 256;
    __half* h_b = h_base + (size_t)(np + na) * 256;
    float* out_p = (float*)d_out;

    int* rp_c = rp;
    int* rp_w = rp + (NP_MAX + 1);
    int* rp_b = rp + 2 * (NP_MAX + 1);

    static cudaStream_t s_csr = nullptr, s_gemm = nullptr;
    static cudaEvent_t ev_root = nullptr, ev_csr = nullptr, ev_gemm = nullptr;
    if (!s_csr) {
        cudaStreamCreateWithFlags(&s_csr, cudaStreamNonBlocking);
        cudaStreamCreateWithFlags(&s_gemm, cudaStreamNonBlocking);
        cudaEventCreateWithFlags(&ev_root, cudaEventDisableTiming);
        cudaEventCreateWithFlags(&ev_csr, cudaEventDisableTiming);
        cudaEventCreateWithFlags(&ev_gemm, cudaEventDisableTiming);
    }
    cudaStream_t s0 = (cudaStream_t)0;

    // fork
    cudaEventRecord(ev_root, s0);
    cudaStreamWaitEvent(s_csr, ev_root, 0);
    cudaStreamWaitEvent(s_gemm, ev_root, 0);

    // branch 1 (default stream): attention logit precursors
    prep_u_kernel<<<1, 256, 0, s0>>>(W_c, as_c, ad_c, W_w, as_w, ad_w, W_b2, as_b, ad_b);
    al_smem_kernel<<<(np + 31) / 32, 256, 0, s0>>>(x_p, U,            alp, np, 16);
    al_smem_kernel<<<(na + 31) / 32, 256, 0, s0>>>(x_a, U + 256 * 16, ala, na, 8);

    // branch 2 (s_csr): CSR build
    int cnt_total = 2 * NP_MAX + NA_MAX;
    int Etot = Ec + Ew + Eb;
    zero_cnt_kernel<<<(cnt_total + 255) / 256, 256, 0, s_csr>>>(cnt_total);
    hist3_kernel<<<(Etot + 255) / 256, 256, 0, s_csr>>>(e_c, Ec, e_w, Ew, e_b, Eb);
    scan3_kernel<<<3, 1024, 0, s_csr>>>(np, na, rp);
    scatter3_kernel<<<(Etot + 255) / 256, 256, 0, s_csr>>>(e_c, Ec, e_w, Ew, e_b, Eb);
    cudaEventRecord(ev_csr, s_csr);

    // branch 3 (s_gemm): projections (two dual launches)
    dim3 gp(4, (np + 127) / 128), ga(2, (na + 127) / 128);
    gemm_tf32_dual_kernel<<<gp, 256, 0, s_gemm>>>(x_p, W_c, W_b2, h_c, h_b, np);
    gemm_tf32_dual_kernel<<<ga, 256, 0, s_gemm>>>(x_a, W_w, W_w, h_w, h_w, na);
    cudaEventRecord(ev_gemm, s_gemm);

    // join on default stream
    cudaStreamWaitEvent(s0, ev_csr, 0);
    cudaStreamWaitEvent(s0, ev_gemm, 0);

    // merged gather aggregation, fused normalize + bias + ELU
    agg_all_kernel<<<((np + na) * 32 + 255) / 256, 256, 0, s0>>>(
        rp_c, rp_w, rp_b, alp, ala, h_c, h_w, h_b,
        b_c, b_w, b_b, out_p, np, na, Ec, Ew);
}